// round 1
// baseline (speedup 1.0000x reference)
#include <cuda_runtime.h>
#include <math_constants.h>

#define B 4
#define S 2048
#define U 1024
#define DK 64
#define NEGC 1.0e9f
#define SCALE 0.125f   // 1/sqrt(64)

// ---------------- scratch (no allocation allowed) ----------------
__device__ float g_Qp[(size_t)B * S * DK];
__device__ float g_Kp[(size_t)B * S * DK];
__device__ float g_Vp[(size_t)B * S * DK];

// ---------------- projection: out[m,n] = X[m,:] . W[n,:] + bias[n] ----------------
// X: [8192,1024], W: [64,1024], out: [8192,64]
// BM=64, BN=64, BK=32, 256 threads, 4x4 micro-tile
#define PBM 64
#define PBN 64
#define PBK 32

__global__ __launch_bounds__(256) void proj_kernel(
    const float* __restrict__ Qx, const float* __restrict__ Wq, const float* __restrict__ bq,
    const float* __restrict__ Kx, const float* __restrict__ Wk, const float* __restrict__ bk,
    const float* __restrict__ Vx, const float* __restrict__ Wv, const float* __restrict__ bv)
{
    __shared__ float Xs[PBK][PBM];   // k-major: conflict-free float4 compute reads
    __shared__ float Ws[PBK][PBN];

    const int which = blockIdx.y;
    const float* X    = (which == 0) ? Qx : (which == 1) ? Kx : Vx;
    const float* W    = (which == 0) ? Wq : (which == 1) ? Wk : Wv;
    const float* bias = (which == 0) ? bq : (which == 1) ? bk : bv;
    float* out = (which == 0) ? g_Qp : (which == 1) ? g_Kp : g_Vp;

    const int tid  = threadIdx.x;
    const int m0   = blockIdx.x * PBM;
    const int trow = tid >> 4;   // 0..15 -> 4 rows each
    const int tcol = tid & 15;   // 0..15 -> 4 cols each

    float acc[4][4] = {};

    for (int k0 = 0; k0 < U; k0 += PBK) {
        // load X tile: 64 rows x 32 k = 512 float4, 2 per thread
        #pragma unroll
        for (int l = 0; l < 2; l++) {
            int idx = tid + l * 256;           // 0..511
            int r = idx >> 3;                  // row 0..63
            int c = idx & 7;                   // float4 in k
            float4 v = *(const float4*)(X + (size_t)(m0 + r) * U + k0 + c * 4);
            Xs[c*4+0][r] = v.x; Xs[c*4+1][r] = v.y; Xs[c*4+2][r] = v.z; Xs[c*4+3][r] = v.w;
        }
        // load W tile: 64 rows x 32 k = 512 float4, 2 per thread
        #pragma unroll
        for (int l = 0; l < 2; l++) {
            int idx = tid + l * 256;
            int n = idx >> 3;
            int c = idx & 7;
            float4 v = *(const float4*)(W + (size_t)n * U + k0 + c * 4);
            Ws[c*4+0][n] = v.x; Ws[c*4+1][n] = v.y; Ws[c*4+2][n] = v.z; Ws[c*4+3][n] = v.w;
        }
        __syncthreads();

        #pragma unroll
        for (int kk = 0; kk < PBK; kk++) {
            float4 a4 = *(const float4*)&Xs[kk][trow * 4];
            float4 b4 = *(const float4*)&Ws[kk][tcol * 4];
            float a[4] = {a4.x, a4.y, a4.z, a4.w};
            float b[4] = {b4.x, b4.y, b4.z, b4.w};
            #pragma unroll
            for (int i = 0; i < 4; i++)
                #pragma unroll
                for (int j = 0; j < 4; j++)
                    acc[i][j] += a[i] * b[j];
        }
        __syncthreads();
    }

    #pragma unroll
    for (int i = 0; i < 4; i++) {
        int m = m0 + trow * 4 + i;
        float4 r4;
        r4.x = acc[i][0] + bias[tcol*4+0];
        r4.y = acc[i][1] + bias[tcol*4+1];
        r4.z = acc[i][2] + bias[tcol*4+2];
        r4.w = acc[i][3] + bias[tcol*4+3];
        *(float4*)(out + (size_t)m * DK + tcol * 4) = r4;
    }
}

// ---------------- fused masked attention, flash-style ----------------
// Per block: 64 queries (full D=64), loop over 32 key tiles of 64.
// 256 threads: qg=tid/16 (4 q-rows each), jg=tid%16 (4 j / 4 d cols each).
#define TQ 64
#define TJ 64
#define PITCH 65
#define SM_FLOATS (4 * 64 * PITCH)

__global__ __launch_bounds__(256) void attn_kernel(
    const int* __restrict__ mask, float* __restrict__ out)
{
    extern __shared__ float smem[];
    float (*Qs)[PITCH] = (float(*)[PITCH])(smem);
    float (*Ks)[PITCH] = (float(*)[PITCH])(smem + 64 * PITCH);
    float (*Vs)[PITCH] = (float(*)[PITCH])(smem + 2 * 64 * PITCH);
    float (*Ps)[PITCH] = (float(*)[PITCH])(smem + 3 * 64 * PITCH);

    const int bb = blockIdx.y;
    const int q0 = blockIdx.x * TQ;
    const int tid = threadIdx.x;
    const int qg = tid >> 4;   // 0..15
    const int jg = tid & 15;   // 0..15

    const float* Qp = g_Qp + ((size_t)bb * S + q0) * DK;
    const float* Kp = g_Kp + (size_t)bb * S * DK;
    const float* Vp = g_Vp + (size_t)bb * S * DK;

    // load Q tile (once): 64x64 floats = 1024 float4, 4 per thread
    #pragma unroll
    for (int l = 0; l < 4; l++) {
        int idx = tid + l * 256;
        int r = idx >> 4;
        int c = idx & 15;
        float4 v = *(const float4*)(Qp + (size_t)r * DK + c * 4);
        Qs[r][c*4+0] = v.x; Qs[r][c*4+1] = v.y; Qs[r][c*4+2] = v.z; Qs[r][c*4+3] = v.w;
    }

    float o[4][4] = {};
    float rmax[4], rsum[4];
    #pragma unroll
    for (int i = 0; i < 4; i++) { rmax[i] = -CUDART_INF_F; rsum[i] = 0.f; }

    for (int j0 = 0; j0 < S; j0 += TJ) {
        __syncthreads();   // prev iter done with Ks/Vs/Ps
        // load K and V tiles
        #pragma unroll
        for (int l = 0; l < 4; l++) {
            int idx = tid + l * 256;
            int r = idx >> 4;
            int c = idx & 15;
            float4 kv = *(const float4*)(Kp + (size_t)(j0 + r) * DK + c * 4);
            Ks[r][c*4+0] = kv.x; Ks[r][c*4+1] = kv.y; Ks[r][c*4+2] = kv.z; Ks[r][c*4+3] = kv.w;
            float4 vv = *(const float4*)(Vp + (size_t)(j0 + r) * DK + c * 4);
            Vs[r][c*4+0] = vv.x; Vs[r][c*4+1] = vv.y; Vs[r][c*4+2] = vv.z; Vs[r][c*4+3] = vv.w;
        }
        __syncthreads();

        // scores: s[i][j] = Q_[q0+qg*4+i] . K_[j0+jg*4+j]
        float s[4][4] = {};
        #pragma unroll 8
        for (int d = 0; d < DK; d++) {
            float a[4], kb[4];
            #pragma unroll
            for (int i = 0; i < 4; i++) a[i] = Qs[qg*4 + i][d];
            #pragma unroll
            for (int j = 0; j < 4; j++) kb[j] = Ks[jg*4 + j][d];
            #pragma unroll
            for (int i = 0; i < 4; i++)
                #pragma unroll
                for (int j = 0; j < 4; j++)
                    s[i][j] += a[i] * kb[j];
        }

        // mask + online softmax (row group = 16 consecutive lanes)
        #pragma unroll
        for (int i = 0; i < 4; i++) {
            const int qrow = q0 + qg * 4 + i;
            int4 mv = *(const int4*)(mask + ((size_t)bb * S + qrow) * S + j0 + jg * 4);
            float ms[4];
            ms[0] = mv.x ? s[i][0] * SCALE : -NEGC;
            ms[1] = mv.y ? s[i][1] * SCALE : -NEGC;
            ms[2] = mv.z ? s[i][2] * SCALE : -NEGC;
            ms[3] = mv.w ? s[i][3] * SCALE : -NEGC;

            float tmax = fmaxf(fmaxf(ms[0], ms[1]), fmaxf(ms[2], ms[3]));
            #pragma unroll
            for (int off = 8; off >= 1; off >>= 1)
                tmax = fmaxf(tmax, __shfl_xor_sync(0xffffffffu, tmax, off));

            float nm = fmaxf(rmax[i], tmax);
            float corr = __expf(rmax[i] - nm);
            rmax[i] = nm;

            float p0 = __expf(ms[0] - nm);
            float p1 = __expf(ms[1] - nm);
            float p2 = __expf(ms[2] - nm);
            float p3 = __expf(ms[3] - nm);
            Ps[qg*4 + i][jg*4 + 0] = p0;
            Ps[qg*4 + i][jg*4 + 1] = p1;
            Ps[qg*4 + i][jg*4 + 2] = p2;
            Ps[qg*4 + i][jg*4 + 3] = p3;

            float psum = p0 + p1 + p2 + p3;
            #pragma unroll
            for (int off = 8; off >= 1; off >>= 1)
                psum += __shfl_xor_sync(0xffffffffu, psum, off);
            rsum[i] = rsum[i] * corr + psum;

            o[i][0] *= corr; o[i][1] *= corr; o[i][2] *= corr; o[i][3] *= corr;
        }
        __syncthreads();   // Ps visible to all

        // PV: o[i][k] += sum_j Ps[q][j] * Vs[j][d]
        #pragma unroll 8
        for (int j = 0; j < TJ; j++) {
            float pr[4], vr[4];
            #pragma unroll
            for (int i = 0; i < 4; i++) pr[i] = Ps[qg*4 + i][j];
            #pragma unroll
            for (int k = 0; k < 4; k++) vr[k] = Vs[j][jg*4 + k];
            #pragma unroll
            for (int i = 0; i < 4; i++)
                #pragma unroll
                for (int k = 0; k < 4; k++)
                    o[i][k] += pr[i] * vr[k];
        }
    }

    // normalize + write
    #pragma unroll
    for (int i = 0; i < 4; i++) {
        float inv = 1.0f / rsum[i];
        float4 r4;
        r4.x = o[i][0] * inv; r4.y = o[i][1] * inv;
        r4.z = o[i][2] * inv; r4.w = o[i][3] * inv;
        *(float4*)(out + ((size_t)bb * S + q0 + qg * 4 + i) * DK + jg * 4) = r4;
    }
}

// ---------------- launch ----------------
extern "C" void kernel_launch(void* const* d_in, const int* in_sizes, int n_in,
                              void* d_out, int out_size)
{
    const float* Q    = (const float*)d_in[0];
    const float* K    = (const float*)d_in[1];
    const float* V    = (const float*)d_in[2];
    const int*   mask = (const int*)  d_in[3];
    const float* Wq   = (const float*)d_in[4];
    const float* bq   = (const float*)d_in[5];
    const float* Wk   = (const float*)d_in[6];
    const float* bk   = (const float*)d_in[7];
    const float* Wv   = (const float*)d_in[8];
    const float* bv   = (const float*)d_in[9];
    float* out = (float*)d_out;

    (void)in_sizes; (void)n_in; (void)out_size;

    // projections: grid (M/64, 3)
    proj_kernel<<<dim3((B * S) / PBM, 3), 256>>>(Q, Wq, bq, K, Wk, bk, V, Wv, bv);

    // attention
    size_t smem_bytes = (size_t)SM_FLOATS * sizeof(float);   // 66560 B
    cudaFuncSetAttribute(attn_kernel, cudaFuncAttributeMaxDynamicSharedMemorySize,
                         (int)smem_bytes);
    attn_kernel<<<dim3(S / TQ, B), 256, smem_bytes>>>(mask, out);
}

// round 3
// speedup vs baseline: 2.3553x; 2.3553x over previous
#include <cuda_runtime.h>
#include <math_constants.h>
#include <cstdint>

#define NB    4
#define SQ    2048
#define UU    1024
#define DKD   64
#define NEGC  1.0e9f
#define SCL   0.125f   // 1/sqrt(64)

// ---------------- scratch (no allocation allowed) ----------------
// g_Qp / g_Kp: [8192][64] tf32-rounded, k-dimension stored PERMUTED:
//   position p in each 8-group holds element k with p = (k<4 ? 2k : 2(k-4)+1)
// g_Vt: [B][64(d)][2048(s)] tf32-rounded, transposed
__device__ float g_Qp[(size_t)NB * SQ * DKD];
__device__ float g_Kp[(size_t)NB * SQ * DKD];
__device__ float g_Vt[(size_t)NB * DKD * SQ];

// ---------------- helpers ----------------
__device__ __forceinline__ float tf32f(float x) {
    uint32_t u;
    asm("cvt.rna.tf32.f32 %0, %1;" : "=r"(u) : "f"(x));
    return __uint_as_float(u);
}
__device__ __forceinline__ uint32_t tf32u(float x) {
    uint32_t u;
    asm("cvt.rna.tf32.f32 %0, %1;" : "=r"(u) : "f"(x));
    return u;
}
__device__ __forceinline__ int kperm(int kk) {   // {0..7} -> {0,2,4,6,1,3,5,7}
    return ((kk & 3) << 1) | (kk >> 2);
}
__device__ __forceinline__ void mma8(float* c,
                                     uint32_t a0, uint32_t a1, uint32_t a2, uint32_t a3,
                                     uint32_t b0, uint32_t b1) {
    asm volatile(
        "mma.sync.aligned.m16n8k8.row.col.f32.tf32.tf32.f32 "
        "{%0,%1,%2,%3}, {%4,%5,%6,%7}, {%8,%9}, {%0,%1,%2,%3};\n"
        : "+f"(c[0]), "+f"(c[1]), "+f"(c[2]), "+f"(c[3])
        : "r"(a0), "r"(a1), "r"(a2), "r"(a3), "r"(b0), "r"(b1));
}

// =======================================================================
// Projection GEMM (tf32 mma): out[m,n] = X[m,:] . W[n,:] + b[n]
// CTA: 128 rows x 64 cols, 8 warps (16 rows each). K chunks of 64.
// =======================================================================
#define XPITCH 72
#define WPITCH 72
#define PROJ_SMEM_FLOATS (128 * XPITCH + 64 * WPITCH)   // 13824 floats = 55296 B

__global__ __launch_bounds__(256, 1) void proj_tc(
    const float* __restrict__ Qx, const float* __restrict__ Wq, const float* __restrict__ bq,
    const float* __restrict__ Kx, const float* __restrict__ Wk, const float* __restrict__ bk,
    const float* __restrict__ Vx, const float* __restrict__ Wv, const float* __restrict__ bv)
{
    extern __shared__ float sm[];
    float* Xs = sm;                    // [128][72]
    float* Ws = sm + 128 * XPITCH;     // [64][72]

    const int which = blockIdx.y;
    const float* X    = (which == 0) ? Qx : (which == 1) ? Kx : Vx;
    const float* W    = (which == 0) ? Wq : (which == 1) ? Wk : Wv;
    const float* bias = (which == 0) ? bq : (which == 1) ? bk : bv;

    const int tid = threadIdx.x;
    const int w   = tid >> 5;
    const int lane = tid & 31;
    const int g = lane >> 2;
    const int t = lane & 3;
    const int m0 = blockIdx.x * 128;

    float acc[8][4] = {};

    for (int kc = 0; kc < 16; kc++) {
        const int k0 = kc * 64;
        // stage X tile (tf32, permuted within 8-groups)
        #pragma unroll
        for (int i = 0; i < 8; i++) {
            int idx = tid + i * 256;
            int r = idx >> 4, c4 = idx & 15;
            float4 v = *(const float4*)(X + (size_t)(m0 + r) * UU + k0 + c4 * 4);
            int cc = c4 * 4;
            float* base = &Xs[r * XPITCH + (cc & 0x38)];
            base[kperm((cc + 0) & 7)] = tf32f(v.x);
            base[kperm((cc + 1) & 7)] = tf32f(v.y);
            base[kperm((cc + 2) & 7)] = tf32f(v.z);
            base[kperm((cc + 3) & 7)] = tf32f(v.w);
        }
        // stage W tile
        #pragma unroll
        for (int i = 0; i < 4; i++) {
            int idx = tid + i * 256;
            int r = idx >> 4, c4 = idx & 15;
            float4 v = *(const float4*)(W + (size_t)r * UU + k0 + c4 * 4);
            int cc = c4 * 4;
            float* base = &Ws[r * WPITCH + (cc & 0x38)];
            base[kperm((cc + 0) & 7)] = tf32f(v.x);
            base[kperm((cc + 1) & 7)] = tf32f(v.y);
            base[kperm((cc + 2) & 7)] = tf32f(v.z);
            base[kperm((cc + 3) & 7)] = tf32f(v.w);
        }
        __syncthreads();

        // A fragments for this chunk (resident)
        uint2 a0r[8], a1r[8];
        const float* xr0 = &Xs[(w * 16 + g) * XPITCH + 2 * t];
        const float* xr1 = &Xs[(w * 16 + 8 + g) * XPITCH + 2 * t];
        #pragma unroll
        for (int ks = 0; ks < 8; ks++) {
            a0r[ks] = *(const uint2*)(xr0 + ks * 8);   // {a0, a2}
            a1r[ks] = *(const uint2*)(xr1 + ks * 8);   // {a1, a3}
        }
        #pragma unroll
        for (int nb = 0; nb < 8; nb++) {
            const float* wr = &Ws[(nb * 8 + g) * WPITCH + 2 * t];
            #pragma unroll
            for (int ks = 0; ks < 8; ks++) {
                uint2 b = *(const uint2*)(wr + ks * 8);
                mma8(acc[nb], a0r[ks].x, a1r[ks].x, a0r[ks].y, a1r[ks].y, b.x, b.y);
            }
        }
        __syncthreads();
    }

    // epilogue
    const int lr0 = w * 16 + g, lr1 = lr0 + 8;
    const int t2 = 2 * t;
    const int pA = (t2 < 4) ? 2 * t2 : 2 * (t2 - 4) + 1;       // perm position of col 2t
    const int pB = (t2 + 1 < 4) ? 2 * (t2 + 1) : 2 * (t2 - 3) + 1;

    if (which < 2) {
        float* dst = (which == 0) ? g_Qp : g_Kp;
        #pragma unroll
        for (int nb = 0; nb < 8; nb++) {
            float b0 = bias[nb * 8 + t2], b1 = bias[nb * 8 + t2 + 1];
            dst[(size_t)(m0 + lr0) * 64 + nb * 8 + pA] = tf32f(acc[nb][0] + b0);
            dst[(size_t)(m0 + lr0) * 64 + nb * 8 + pB] = tf32f(acc[nb][1] + b1);
            dst[(size_t)(m0 + lr1) * 64 + nb * 8 + pA] = tf32f(acc[nb][2] + b0);
            dst[(size_t)(m0 + lr1) * 64 + nb * 8 + pB] = tf32f(acc[nb][3] + b1);
        }
    } else {
        // V: transpose through smem, then coalesced store to g_Vt[b][d][s]
        float* ob = sm;   // reuse, pitch 68: [128][68]
        #pragma unroll
        for (int nb = 0; nb < 8; nb++) {
            float b0 = bias[nb * 8 + t2], b1 = bias[nb * 8 + t2 + 1];
            ob[lr0 * 68 + nb * 8 + t2]     = tf32f(acc[nb][0] + b0);
            ob[lr0 * 68 + nb * 8 + t2 + 1] = tf32f(acc[nb][1] + b1);
            ob[lr1 * 68 + nb * 8 + t2]     = tf32f(acc[nb][2] + b0);
            ob[lr1 * 68 + nb * 8 + t2 + 1] = tf32f(acc[nb][3] + b1);
        }
        __syncthreads();
        const int bidx = m0 >> 11;
        const int sbase = m0 & 2047;
        #pragma unroll
        for (int i = 0; i < 8; i++) {
            int idx = tid + i * 256;      // 2048 = 64 d * 32 m-groups
            int d = idx >> 5, mg = idx & 31;
            float4 v;
            v.x = ob[(mg * 4 + 0) * 68 + d];
            v.y = ob[(mg * 4 + 1) * 68 + d];
            v.z = ob[(mg * 4 + 2) * 68 + d];
            v.w = ob[(mg * 4 + 3) * 68 + d];
            *(float4*)(g_Vt + ((size_t)(bidx * 64 + d)) * 2048 + sbase + mg * 4) = v;
        }
    }
}

// =======================================================================
// Flash attention with tf32 mma.sync
// CTA: 64 queries, 8 warps = 4 q-blocks(16) x 2 key-halves(64).
// 16 KV tiles of 128 keys.
// =======================================================================
#define QPITCH 72
#define KPITCH 72
#define VPITCH 136
#define O_QS   0
#define O_KS   (64 * QPITCH)                 // 4608
#define O_VT   (O_KS + 128 * KPITCH)         // 13824
#define O_PMAX (O_VT + 64 * VPITCH)          // 22528
#define O_PSUM (O_PMAX + 128)
#define O_LB   (O_PSUM + 128)
#define ATT_SMEM_FLOATS (O_LB + 64)          // 22848 floats = 91392 B
#define O_OB   O_KS                          // reuse K region for output combine (pitch 68)

__global__ __launch_bounds__(256, 1) void attn_tc(
    const int* __restrict__ mask, float* __restrict__ out)
{
    extern __shared__ float sm[];
    const int tid = threadIdx.x;
    const int w = tid >> 5;
    const int lane = tid & 31;
    const int g = lane >> 2;
    const int t = lane & 3;
    const int qb = w >> 1;     // q-block 0..3
    const int h  = w & 1;      // key half
    const int bb = blockIdx.x >> 5;
    const int q0 = (blockIdx.x & 31) * 64;

    // stage Q tile (already tf32 + permuted in gmem)
    const float* Qg = g_Qp + ((size_t)(bb * SQ + q0)) * 64;
    #pragma unroll
    for (int i = 0; i < 4; i++) {
        int idx = tid + i * 256;
        int r = idx >> 4, c4 = idx & 15;
        *(float4*)&sm[O_QS + r * QPITCH + c4 * 4] =
            *(const float4*)(Qg + (size_t)r * 64 + c4 * 4);
    }
    __syncthreads();

    // resident Q fragments
    uint2 qa0[8], qa1[8];
    {
        const float* r0p = &sm[O_QS + (qb * 16 + g) * QPITCH + 2 * t];
        const float* r1p = &sm[O_QS + (qb * 16 + 8 + g) * QPITCH + 2 * t];
        #pragma unroll
        for (int ks = 0; ks < 8; ks++) {
            qa0[ks] = *(const uint2*)(r0p + ks * 8);   // {a0, a2}
            qa1[ks] = *(const uint2*)(r1p + ks * 8);   // {a1, a3}
        }
    }

    float m0r = -CUDART_INF_F, m1r = -CUDART_INF_F;
    float l0r = 0.f, l1r = 0.f;
    float o[8][4] = {};

    const int row0 = q0 + qb * 16 + g, row1 = row0 + 8;
    const int* mk0 = mask + ((size_t)(bb * SQ + row0)) * SQ;
    const int* mk1 = mask + ((size_t)(bb * SQ + row1)) * SQ;
    const float* Kg = g_Kp + ((size_t)bb * SQ) * 64;
    const float* Vg = g_Vt + ((size_t)bb * 64) * 2048;

    for (int tile = 0; tile < 16; tile++) {
        const int j0 = tile * 128;

        // prefetch mask (independent of smem)
        int2 mv0[8], mv1[8];
        #pragma unroll
        for (int nb = 0; nb < 8; nb++) {
            mv0[nb] = *(const int2*)(mk0 + j0 + h * 64 + nb * 8 + 2 * t);
            mv1[nb] = *(const int2*)(mk1 + j0 + h * 64 + nb * 8 + 2 * t);
        }

        __syncthreads();   // prev tile fully consumed
        // stage K tile (straight copy: layout already permuted)
        #pragma unroll
        for (int i = 0; i < 8; i++) {
            int idx = tid + i * 256;
            int r = idx >> 4, c4 = idx & 15;
            *(float4*)&sm[O_KS + r * KPITCH + c4 * 4] =
                *(const float4*)(Kg + (size_t)(j0 + r) * 64 + c4 * 4);
        }
        // stage V^T tile (straight copy)
        #pragma unroll
        for (int i = 0; i < 8; i++) {
            int idx = tid + i * 256;
            int d = idx >> 5, c4 = idx & 31;
            *(float4*)&sm[O_VT + d * VPITCH + c4 * 4] =
                *(const float4*)(Vg + (size_t)d * 2048 + j0 + c4 * 4);
        }
        __syncthreads();

        // ---- MMA1: scores (this warp: 16 q x 64 j half) ----
        float sa[8][4] = {};
        #pragma unroll
        for (int nb = 0; nb < 8; nb++) {
            const float* kr = &sm[O_KS + (h * 64 + nb * 8 + g) * KPITCH + 2 * t];
            #pragma unroll
            for (int ks = 0; ks < 8; ks++) {
                uint2 b = *(const uint2*)(kr + ks * 8);
                mma8(sa[nb], qa0[ks].x, qa1[ks].x, qa0[ks].y, qa1[ks].y, b.x, b.y);
            }
        }

        // ---- mask + scale ----
        #pragma unroll
        for (int nb = 0; nb < 8; nb++) {
            sa[nb][0] = mv0[nb].x ? sa[nb][0] * SCL : -NEGC;
            sa[nb][1] = mv0[nb].y ? sa[nb][1] * SCL : -NEGC;
            sa[nb][2] = mv1[nb].x ? sa[nb][2] * SCL : -NEGC;
            sa[nb][3] = mv1[nb].y ? sa[nb][3] * SCL : -NEGC;
        }

        // ---- row max (quad reduce + cross-half via smem) ----
        float mx0 = -CUDART_INF_F, mx1 = -CUDART_INF_F;
        #pragma unroll
        for (int nb = 0; nb < 8; nb++) {
            mx0 = fmaxf(mx0, fmaxf(sa[nb][0], sa[nb][1]));
            mx1 = fmaxf(mx1, fmaxf(sa[nb][2], sa[nb][3]));
        }
        mx0 = fmaxf(mx0, __shfl_xor_sync(0xffffffffu, mx0, 1));
        mx0 = fmaxf(mx0, __shfl_xor_sync(0xffffffffu, mx0, 2));
        mx1 = fmaxf(mx1, __shfl_xor_sync(0xffffffffu, mx1, 1));
        mx1 = fmaxf(mx1, __shfl_xor_sync(0xffffffffu, mx1, 2));
        if (t == 0) {
            sm[O_PMAX + h * 64 + qb * 16 + g]     = mx0;
            sm[O_PMAX + h * 64 + qb * 16 + 8 + g] = mx1;
        }
        __syncthreads();
        float fm0 = fmaxf(sm[O_PMAX + qb * 16 + g],     sm[O_PMAX + 64 + qb * 16 + g]);
        float fm1 = fmaxf(sm[O_PMAX + qb * 16 + 8 + g], sm[O_PMAX + 64 + qb * 16 + 8 + g]);
        float nm0 = fmaxf(m0r, fm0), nm1 = fmaxf(m1r, fm1);
        float c0 = __expf(m0r - nm0), c1 = __expf(m1r - nm1);
        m0r = nm0; m1r = nm1;

        // ---- exp + partial sums; P stays in registers as MMA2 A fragments ----
        uint32_t pt[8][4];
        float s0 = 0.f, s1 = 0.f;
        #pragma unroll
        for (int nb = 0; nb < 8; nb++) {
            float p0 = __expf(sa[nb][0] - nm0);
            float p1 = __expf(sa[nb][1] - nm0);
            float p2 = __expf(sa[nb][2] - nm1);
            float p3 = __expf(sa[nb][3] - nm1);
            s0 += p0 + p1; s1 += p2 + p3;
            pt[nb][0] = tf32u(p0); pt[nb][1] = tf32u(p1);
            pt[nb][2] = tf32u(p2); pt[nb][3] = tf32u(p3);
        }
        s0 += __shfl_xor_sync(0xffffffffu, s0, 1);
        s0 += __shfl_xor_sync(0xffffffffu, s0, 2);
        s1 += __shfl_xor_sync(0xffffffffu, s1, 1);
        s1 += __shfl_xor_sync(0xffffffffu, s1, 2);
        if (t == 0) {
            sm[O_PSUM + h * 64 + qb * 16 + g]     = s0;
            sm[O_PSUM + h * 64 + qb * 16 + 8 + g] = s1;
        }

        // rescale running O (overlaps with sync)
        #pragma unroll
        for (int nb = 0; nb < 8; nb++) {
            o[nb][0] *= c0; o[nb][1] *= c0;
            o[nb][2] *= c1; o[nb][3] *= c1;
        }
        __syncthreads();
        l0r = l0r * c0 + sm[O_PSUM + qb * 16 + g]     + sm[O_PSUM + 64 + qb * 16 + g];
        l1r = l1r * c1 + sm[O_PSUM + qb * 16 + 8 + g] + sm[O_PSUM + 64 + qb * 16 + 8 + g];

        // ---- MMA2: O += P . V  (A = score fragments directly) ----
        #pragma unroll
        for (int nd = 0; nd < 8; nd++) {
            const float* vr = &sm[O_VT + (nd * 8 + g) * VPITCH + h * 64 + 2 * t];
            #pragma unroll
            for (int ks = 0; ks < 8; ks++) {
                uint2 b = *(const uint2*)(vr + ks * 8);
                mma8(o[nd], pt[ks][0], pt[ks][2], pt[ks][1], pt[ks][3], b.x, b.y);
            }
        }
    }

    // ---- combine the two key-halves + write out ----
    __syncthreads();
    float* ob = &sm[O_OB];   // [64][68]
    const int lr0 = qb * 16 + g, lr1 = lr0 + 8;
    if (h == 1) {
        #pragma unroll
        for (int nd = 0; nd < 8; nd++) {
            ob[lr0 * 68 + nd * 8 + 2 * t]     = o[nd][0];
            ob[lr0 * 68 + nd * 8 + 2 * t + 1] = o[nd][1];
            ob[lr1 * 68 + nd * 8 + 2 * t]     = o[nd][2];
            ob[lr1 * 68 + nd * 8 + 2 * t + 1] = o[nd][3];
        }
    }
    __syncthreads();
    if (h == 0) {
        #pragma unroll
        for (int nd = 0; nd < 8; nd++) {
            ob[lr0 * 68 + nd * 8 + 2 * t]     += o[nd][0];
            ob[lr0 * 68 + nd * 8 + 2 * t + 1] += o[nd][1];
            ob[lr1 * 68 + nd * 8 + 2 * t]     += o[nd][2];
            ob[lr1 * 68 + nd * 8 + 2 * t + 1] += o[nd][3];
        }
        if (t == 0) {
            sm[O_LB + lr0] = l0r;
            sm[O_LB + lr1] = l1r;
        }
    }
    __syncthreads();
    float* og = out + ((size_t)(bb * SQ + q0)) * 64;
    #pragma unroll
    for (int i = 0; i < 4; i++) {
        int idx = tid + i * 256;
        int r = idx >> 4, c4 = idx & 15;
        float inv = 1.0f / sm[O_LB + r];
        float4 v;
        v.x = ob[r * 68 + c4 * 4 + 0] * inv;
        v.y = ob[r * 68 + c4 * 4 + 1] * inv;
        v.z = ob[r * 68 + c4 * 4 + 2] * inv;
        v.w = ob[r * 68 + c4 * 4 + 3] * inv;
        *(float4*)(og + (size_t)r * 64 + c4 * 4) = v;
    }
}

// ---------------- launch ----------------
extern "C" void kernel_launch(void* const* d_in, const int* in_sizes, int n_in,
                              void* d_out, int out_size)
{
    const float* Q    = (const float*)d_in[0];
    const float* K    = (const float*)d_in[1];
    const float* V    = (const float*)d_in[2];
    const int*   mask = (const int*)  d_in[3];
    const float* Wq   = (const float*)d_in[4];
    const float* bq   = (const float*)d_in[5];
    const float* Wk   = (const float*)d_in[6];
    const float* bk   = (const float*)d_in[7];
    const float* Wv   = (const float*)d_in[8];
    const float* bv   = (const float*)d_in[9];
    float* out = (float*)d_out;

    (void)in_sizes; (void)n_in; (void)out_size;

    const int proj_smem = PROJ_SMEM_FLOATS * 4;   // 55296
    const int att_smem  = ATT_SMEM_FLOATS * 4;    // 91392
    cudaFuncSetAttribute(proj_tc, cudaFuncAttributeMaxDynamicSharedMemorySize, proj_smem);
    cudaFuncSetAttribute(attn_tc, cudaFuncAttributeMaxDynamicSharedMemorySize, att_smem);

    proj_tc<<<dim3(64, 3), 256, proj_smem>>>(Q, Wq, bq, K, Wk, bk, V, Wv, bv);
    attn_tc<<<dim3(128), 256, att_smem>>>(mask, out);
}

// round 4
// speedup vs baseline: 3.0360x; 1.2890x over previous
#include <cuda_runtime.h>
#include <math_constants.h>
#include <cstdint>

#define NB    4
#define SQ    2048
#define UU    1024
#define DKD   64
#define NEGC  1.0e9f
#define SCL   0.125f   // 1/sqrt(64)
#define NSPL  2        // key splits

// ---------------- scratch (no allocation allowed) ----------------
// g_Qp / g_Kp: [8192][64] tf32-rounded, k-dim PERMUTED within 8-groups:
//   position p holds element k with p = (k<4 ? 2k : 2(k-4)+1)
// g_Vt: [B][64(d)][2048(s)] tf32-rounded, transposed
__device__ float g_Qp[(size_t)NB * SQ * DKD];
__device__ float g_Kp[(size_t)NB * SQ * DKD];
__device__ float g_Vt[(size_t)NB * DKD * SQ];
// split-K partials: [split][b*S+s]
__device__ float g_Po[(size_t)NSPL * NB * SQ * DKD];   // unnormalized partial O
__device__ float g_Pm[(size_t)NSPL * NB * SQ];         // running max
__device__ float g_Pl[(size_t)NSPL * NB * SQ];         // running sum

// ---------------- helpers ----------------
__device__ __forceinline__ float tf32f(float x) {
    uint32_t u;
    asm("cvt.rna.tf32.f32 %0, %1;" : "=r"(u) : "f"(x));
    return __uint_as_float(u);
}
__device__ __forceinline__ uint32_t tf32u(float x) {
    uint32_t u;
    asm("cvt.rna.tf32.f32 %0, %1;" : "=r"(u) : "f"(x));
    return u;
}
__device__ __forceinline__ void mma8(float* c,
                                     uint32_t a0, uint32_t a1, uint32_t a2, uint32_t a3,
                                     uint32_t b0, uint32_t b1) {
    asm volatile(
        "mma.sync.aligned.m16n8k8.row.col.f32.tf32.tf32.f32 "
        "{%0,%1,%2,%3}, {%4,%5,%6,%7}, {%8,%9}, {%0,%1,%2,%3};\n"
        : "+f"(c[0]), "+f"(c[1]), "+f"(c[2]), "+f"(c[3])
        : "r"(a0), "r"(a1), "r"(a2), "r"(a3), "r"(b0), "r"(b1));
}

// =======================================================================
// Projection GEMM (tf32 mma): out[m,n] = X[m,:] . W[n,:] + b[n]
// CTA: 128 rows x 64 cols, 8 warps (16 rows each). K chunks of 64.
// Staging: register re-pack into permuted layout -> 2x STS.128 per 8-group.
// =======================================================================
#define XPITCH 72
#define WPITCH 72
#define PROJ_SMEM_FLOATS (128 * XPITCH + 64 * WPITCH)   // 13824 floats = 55296 B

__global__ __launch_bounds__(256, 1) void proj_tc(
    const float* __restrict__ Qx, const float* __restrict__ Wq, const float* __restrict__ bq,
    const float* __restrict__ Kx, const float* __restrict__ Wk, const float* __restrict__ bk,
    const float* __restrict__ Vx, const float* __restrict__ Wv, const float* __restrict__ bv)
{
    extern __shared__ float sm[];
    float* Xs = sm;                    // [128][72]
    float* Ws = sm + 128 * XPITCH;     // [64][72]

    const int which = blockIdx.y;
    const float* X    = (which == 0) ? Qx : (which == 1) ? Kx : Vx;
    const float* W    = (which == 0) ? Wq : (which == 1) ? Wk : Wv;
    const float* bias = (which == 0) ? bq : (which == 1) ? bk : bv;

    const int tid = threadIdx.x;
    const int w   = tid >> 5;
    const int lane = tid & 31;
    const int g = lane >> 2;
    const int t = lane & 3;
    const int m0 = blockIdx.x * 128;

    float acc[8][4] = {};

    for (int kc = 0; kc < 16; kc++) {
        const int k0 = kc * 64;
        // stage X tile: 128 rows x 8 k-groups, 4 groups/thread
        #pragma unroll
        for (int i = 0; i < 4; i++) {
            int gidx = tid + i * 256;
            int r = gidx >> 3, kg = gidx & 7;
            const float* src = X + (size_t)(m0 + r) * UU + k0 + kg * 8;
            float4 lo = *(const float4*)(src);
            float4 hi = *(const float4*)(src + 4);
            float* dstp = &Xs[r * XPITCH + kg * 8];
            uint4 s1 = make_uint4(tf32u(lo.x), tf32u(hi.x), tf32u(lo.y), tf32u(hi.y));
            uint4 s2 = make_uint4(tf32u(lo.z), tf32u(hi.z), tf32u(lo.w), tf32u(hi.w));
            *(uint4*)(dstp)     = s1;
            *(uint4*)(dstp + 4) = s2;
        }
        // stage W tile: 64 rows x 8 groups, 2 groups/thread
        #pragma unroll
        for (int i = 0; i < 2; i++) {
            int gidx = tid + i * 256;
            int r = gidx >> 3, kg = gidx & 7;
            const float* src = W + (size_t)r * UU + k0 + kg * 8;
            float4 lo = *(const float4*)(src);
            float4 hi = *(const float4*)(src + 4);
            float* dstp = &Ws[r * WPITCH + kg * 8];
            uint4 s1 = make_uint4(tf32u(lo.x), tf32u(hi.x), tf32u(lo.y), tf32u(hi.y));
            uint4 s2 = make_uint4(tf32u(lo.z), tf32u(hi.z), tf32u(lo.w), tf32u(hi.w));
            *(uint4*)(dstp)     = s1;
            *(uint4*)(dstp + 4) = s2;
        }
        __syncthreads();

        uint2 a0r[8], a1r[8];
        const float* xr0 = &Xs[(w * 16 + g) * XPITCH + 2 * t];
        const float* xr1 = &Xs[(w * 16 + 8 + g) * XPITCH + 2 * t];
        #pragma unroll
        for (int ks = 0; ks < 8; ks++) {
            a0r[ks] = *(const uint2*)(xr0 + ks * 8);   // {a0, a2}
            a1r[ks] = *(const uint2*)(xr1 + ks * 8);   // {a1, a3}
        }
        #pragma unroll
        for (int nb = 0; nb < 8; nb++) {
            const float* wr = &Ws[(nb * 8 + g) * WPITCH + 2 * t];
            #pragma unroll
            for (int ks = 0; ks < 8; ks++) {
                uint2 b = *(const uint2*)(wr + ks * 8);
                mma8(acc[nb], a0r[ks].x, a1r[ks].x, a0r[ks].y, a1r[ks].y, b.x, b.y);
            }
        }
        __syncthreads();
    }

    // epilogue
    const int lr0 = w * 16 + g, lr1 = lr0 + 8;
    const int t2 = 2 * t;
    const int pA = (t2 < 4) ? 2 * t2 : 2 * (t2 - 4) + 1;
    const int pB = (t2 + 1 < 4) ? 2 * (t2 + 1) : 2 * (t2 - 3) + 1;

    if (which < 2) {
        float* dst = (which == 0) ? g_Qp : g_Kp;
        #pragma unroll
        for (int nb = 0; nb < 8; nb++) {
            float b0 = bias[nb * 8 + t2], b1 = bias[nb * 8 + t2 + 1];
            dst[(size_t)(m0 + lr0) * 64 + nb * 8 + pA] = tf32f(acc[nb][0] + b0);
            dst[(size_t)(m0 + lr0) * 64 + nb * 8 + pB] = tf32f(acc[nb][1] + b1);
            dst[(size_t)(m0 + lr1) * 64 + nb * 8 + pA] = tf32f(acc[nb][2] + b0);
            dst[(size_t)(m0 + lr1) * 64 + nb * 8 + pB] = tf32f(acc[nb][3] + b1);
        }
    } else {
        // V: transpose through smem, coalesced store to g_Vt[b][d][s]
        float* ob = sm;   // reuse, pitch 68: [128][68]
        #pragma unroll
        for (int nb = 0; nb < 8; nb++) {
            float b0 = bias[nb * 8 + t2], b1 = bias[nb * 8 + t2 + 1];
            ob[lr0 * 68 + nb * 8 + t2]     = tf32f(acc[nb][0] + b0);
            ob[lr0 * 68 + nb * 8 + t2 + 1] = tf32f(acc[nb][1] + b1);
            ob[lr1 * 68 + nb * 8 + t2]     = tf32f(acc[nb][2] + b0);
            ob[lr1 * 68 + nb * 8 + t2 + 1] = tf32f(acc[nb][3] + b1);
        }
        __syncthreads();
        const int bidx = m0 >> 11;
        const int sbase = m0 & 2047;
        #pragma unroll
        for (int i = 0; i < 8; i++) {
            int idx = tid + i * 256;
            int d = idx >> 5, mg = idx & 31;
            float4 v;
            v.x = ob[(mg * 4 + 0) * 68 + d];
            v.y = ob[(mg * 4 + 1) * 68 + d];
            v.z = ob[(mg * 4 + 2) * 68 + d];
            v.w = ob[(mg * 4 + 3) * 68 + d];
            *(float4*)(g_Vt + ((size_t)(bidx * 64 + d)) * 2048 + sbase + mg * 4) = v;
        }
    }
}

// =======================================================================
// Flash attention, split-K: CTA = 4 warps x 16 full query rows, 1024 keys.
// grid (32 q-tiles, 2 splits, 4 batches) = 256 CTAs. 8 KV tiles of 128.
// =======================================================================
#define QPITCH 72
#define KPITCH 72
#define VPITCH 136
#define A_QS   0
#define A_KS   (64 * QPITCH)                 // 4608
#define A_VT   (A_KS + 128 * KPITCH)         // 13824
#define ATT_SMEM_FLOATS (A_VT + 64 * VPITCH) // 22528 floats = 90112 B

__global__ __launch_bounds__(128, 2) void attn_tc(
    const int* __restrict__ mask)
{
    extern __shared__ float sm[];
    const int tid = threadIdx.x;
    const int w = tid >> 5;
    const int lane = tid & 31;
    const int g = lane >> 2;
    const int t = lane & 3;
    const int qt = blockIdx.x;
    const int sp = blockIdx.y;
    const int bb = blockIdx.z;
    const int q0 = qt * 64;
    const int kbase = sp * (SQ / NSPL);

    // stage Q tile (already tf32 + permuted)
    const float* Qg = g_Qp + ((size_t)(bb * SQ + q0)) * 64;
    #pragma unroll
    for (int i = 0; i < 8; i++) {
        int idx = tid + i * 128;
        int r = idx >> 4, c4 = idx & 15;
        *(float4*)&sm[A_QS + r * QPITCH + c4 * 4] =
            *(const float4*)(Qg + (size_t)r * 64 + c4 * 4);
    }
    __syncthreads();

    // resident Q fragments (this warp's 16 rows)
    uint2 qa0[8], qa1[8];
    {
        const float* r0p = &sm[A_QS + (w * 16 + g) * QPITCH + 2 * t];
        const float* r1p = &sm[A_QS + (w * 16 + 8 + g) * QPITCH + 2 * t];
        #pragma unroll
        for (int ks = 0; ks < 8; ks++) {
            qa0[ks] = *(const uint2*)(r0p + ks * 8);
            qa1[ks] = *(const uint2*)(r1p + ks * 8);
        }
    }

    float m0r = -CUDART_INF_F, m1r = -CUDART_INF_F;
    float l0r = 0.f, l1r = 0.f;
    float o[8][4] = {};

    const int row0 = q0 + w * 16 + g, row1 = row0 + 8;
    const int* mk0 = mask + ((size_t)(bb * SQ + row0)) * SQ + kbase;
    const int* mk1 = mask + ((size_t)(bb * SQ + row1)) * SQ + kbase;
    const float* Kg = g_Kp + ((size_t)(bb * SQ + kbase)) * 64;
    const float* Vg = g_Vt + ((size_t)bb * 64) * 2048 + kbase;

    for (int tile = 0; tile < (SQ / NSPL) / 128; tile++) {
        const int j0 = tile * 128;

        __syncthreads();   // prev tile fully consumed
        // stage K tile (straight copy, perm layout)
        #pragma unroll
        for (int i = 0; i < 16; i++) {
            int idx = tid + i * 128;
            int r = idx >> 4, c4 = idx & 15;
            *(float4*)&sm[A_KS + r * KPITCH + c4 * 4] =
                *(const float4*)(Kg + (size_t)(j0 + r) * 64 + c4 * 4);
        }
        // stage V^T tile (straight copy)
        #pragma unroll
        for (int i = 0; i < 16; i++) {
            int idx = tid + i * 128;
            int d = idx >> 5, c4 = idx & 31;
            *(float4*)&sm[A_VT + d * VPITCH + c4 * 4] =
                *(const float4*)(Vg + (size_t)d * 2048 + j0 + c4 * 4);
        }
        __syncthreads();

        // ---- MMA1: scores 16q x 128j ----
        float sa[16][4];
        #pragma unroll
        for (int nb = 0; nb < 16; nb++) {
            sa[nb][0] = 0.f; sa[nb][1] = 0.f; sa[nb][2] = 0.f; sa[nb][3] = 0.f;
            const float* kr = &sm[A_KS + (nb * 8 + g) * KPITCH + 2 * t];
            #pragma unroll
            for (int ks = 0; ks < 8; ks++) {
                uint2 b = *(const uint2*)(kr + ks * 8);
                mma8(sa[nb], qa0[ks].x, qa1[ks].x, qa0[ks].y, qa1[ks].y, b.x, b.y);
            }
        }

        // ---- mask + scale ----
        #pragma unroll
        for (int nb = 0; nb < 16; nb++) {
            int2 mv0 = *(const int2*)(mk0 + j0 + nb * 8 + 2 * t);
            int2 mv1 = *(const int2*)(mk1 + j0 + nb * 8 + 2 * t);
            sa[nb][0] = mv0.x ? sa[nb][0] * SCL : -NEGC;
            sa[nb][1] = mv0.y ? sa[nb][1] * SCL : -NEGC;
            sa[nb][2] = mv1.x ? sa[nb][2] * SCL : -NEGC;
            sa[nb][3] = mv1.y ? sa[nb][3] * SCL : -NEGC;
        }

        // ---- row max (full row within warp: quad reduce only) ----
        float mx0 = -CUDART_INF_F, mx1 = -CUDART_INF_F;
        #pragma unroll
        for (int nb = 0; nb < 16; nb++) {
            mx0 = fmaxf(mx0, fmaxf(sa[nb][0], sa[nb][1]));
            mx1 = fmaxf(mx1, fmaxf(sa[nb][2], sa[nb][3]));
        }
        mx0 = fmaxf(mx0, __shfl_xor_sync(0xffffffffu, mx0, 1));
        mx0 = fmaxf(mx0, __shfl_xor_sync(0xffffffffu, mx0, 2));
        mx1 = fmaxf(mx1, __shfl_xor_sync(0xffffffffu, mx1, 1));
        mx1 = fmaxf(mx1, __shfl_xor_sync(0xffffffffu, mx1, 2));

        float nm0 = fmaxf(m0r, mx0), nm1 = fmaxf(m1r, mx1);
        float c0 = __expf(m0r - nm0), c1 = __expf(m1r - nm1);
        m0r = nm0; m1r = nm1;

        // ---- exp (in place, tf32) + sums ----
        float s0 = 0.f, s1 = 0.f;
        #pragma unroll
        for (int nb = 0; nb < 16; nb++) {
            float p0 = __expf(sa[nb][0] - nm0);
            float p1 = __expf(sa[nb][1] - nm0);
            float p2 = __expf(sa[nb][2] - nm1);
            float p3 = __expf(sa[nb][3] - nm1);
            s0 += p0 + p1; s1 += p2 + p3;
            sa[nb][0] = __uint_as_float(tf32u(p0));
            sa[nb][1] = __uint_as_float(tf32u(p1));
            sa[nb][2] = __uint_as_float(tf32u(p2));
            sa[nb][3] = __uint_as_float(tf32u(p3));
        }
        s0 += __shfl_xor_sync(0xffffffffu, s0, 1);
        s0 += __shfl_xor_sync(0xffffffffu, s0, 2);
        s1 += __shfl_xor_sync(0xffffffffu, s1, 1);
        s1 += __shfl_xor_sync(0xffffffffu, s1, 2);
        l0r = l0r * c0 + s0;
        l1r = l1r * c1 + s1;

        // rescale running O
        #pragma unroll
        for (int nd = 0; nd < 8; nd++) {
            o[nd][0] *= c0; o[nd][1] *= c0;
            o[nd][2] *= c1; o[nd][3] *= c1;
        }

        // ---- MMA2: O += P . V  (A = score fragments directly) ----
        #pragma unroll
        for (int nd = 0; nd < 8; nd++) {
            const float* vr = &sm[A_VT + (nd * 8 + g) * VPITCH + 2 * t];
            #pragma unroll
            for (int ks = 0; ks < 16; ks++) {
                uint2 b = *(const uint2*)(vr + ks * 8);
                mma8(o[nd],
                     __float_as_uint(sa[ks][0]), __float_as_uint(sa[ks][2]),
                     __float_as_uint(sa[ks][1]), __float_as_uint(sa[ks][3]),
                     b.x, b.y);
            }
        }
    }

    // ---- write split partials (unnormalized) ----
    const size_t sr0 = (size_t)sp * (NB * SQ) + (size_t)bb * SQ + row0;
    const size_t sr1 = sr0 + 8;
    #pragma unroll
    for (int nd = 0; nd < 8; nd++) {
        *(float2*)(g_Po + sr0 * 64 + nd * 8 + 2 * t) = make_float2(o[nd][0], o[nd][1]);
        *(float2*)(g_Po + sr1 * 64 + nd * 8 + 2 * t) = make_float2(o[nd][2], o[nd][3]);
    }
    if (t == 0) {
        g_Pm[sr0] = m0r; g_Pl[sr0] = l0r;
        g_Pm[sr1] = m1r; g_Pl[sr1] = l1r;
    }
}

// =======================================================================
// split combine
// =======================================================================
__global__ __launch_bounds__(256) void combine_k(float* __restrict__ out)
{
    int gid = blockIdx.x * 256 + threadIdx.x;   // 8192 rows * 16 float4
    int row = gid >> 4;
    int c4 = gid & 15;
    float m1 = g_Pm[row], m2 = g_Pm[NB * SQ + row];
    float l1 = g_Pl[row], l2 = g_Pl[NB * SQ + row];
    float m = fmaxf(m1, m2);
    float w1 = __expf(m1 - m), w2 = __expf(m2 - m);
    float inv = 1.0f / (w1 * l1 + w2 * l2);
    w1 *= inv; w2 *= inv;
    float4 o1 = *(const float4*)(g_Po + (size_t)row * 64 + c4 * 4);
    float4 o2 = *(const float4*)(g_Po + ((size_t)(NB * SQ + row)) * 64 + c4 * 4);
    float4 r;
    r.x = o1.x * w1 + o2.x * w2;
    r.y = o1.y * w1 + o2.y * w2;
    r.z = o1.z * w1 + o2.z * w2;
    r.w = o1.w * w1 + o2.w * w2;
    *(float4*)(out + (size_t)row * 64 + c4 * 4) = r;
}

// ---------------- launch ----------------
extern "C" void kernel_launch(void* const* d_in, const int* in_sizes, int n_in,
                              void* d_out, int out_size)
{
    const float* Q    = (const float*)d_in[0];
    const float* K    = (const float*)d_in[1];
    const float* V    = (const float*)d_in[2];
    const int*   mask = (const int*)  d_in[3];
    const float* Wq   = (const float*)d_in[4];
    const float* bq   = (const float*)d_in[5];
    const float* Wk   = (const float*)d_in[6];
    const float* bk   = (const float*)d_in[7];
    const float* Wv   = (const float*)d_in[8];
    const float* bv   = (const float*)d_in[9];
    float* out = (float*)d_out;

    (void)in_sizes; (void)n_in; (void)out_size;

    const int proj_smem = PROJ_SMEM_FLOATS * 4;   // 55296
    const int att_smem  = ATT_SMEM_FLOATS * 4;    // 90112
    cudaFuncSetAttribute(proj_tc, cudaFuncAttributeMaxDynamicSharedMemorySize, proj_smem);
    cudaFuncSetAttribute(attn_tc, cudaFuncAttributeMaxDynamicSharedMemorySize, att_smem);

    proj_tc<<<dim3(64, 3), 256, proj_smem>>>(Q, Wq, bq, K, Wk, bk, V, Wv, bv);
    attn_tc<<<dim3(32, NSPL, NB), 128, att_smem>>>(mask);
    combine_k<<<(NB * SQ * 16) / 256, 256>>>(out);
}